// round 2
// baseline (speedup 1.0000x reference)
#include <cuda_runtime.h>
#include <math.h>

#define Bm   32
#define Tm   2048
#define Fm   64
#define Hm   256
#define G3   768
#define OUTm 64
#define NCTA 64
#define JPC  4      // hidden units per CTA (NCTA*JPC == Hm)

// ---------------- scratch (device globals; no allocation allowed) ----------
__device__ float d_xnT[Tm * Fm * Bm];        // [t][f][b]      16.8 MB
__device__ float d_xb1[(size_t)Tm * G3 * Bm]; // [t][c][b]     201 MB
__device__ float d_h1 [(size_t)Tm * Hm * Bm]; // [t][k][b]      67 MB
__device__ float d_xb2[(size_t)Tm * G3 * Bm]; // [t][c][b]     201 MB
__device__ float d_hA[Hm * Bm];
__device__ float d_hB[Hm * Bm];
__device__ unsigned d_bar;

// ---------------- LayerNorm:  x[B][T][F] -> xnT[t][f][b] --------------------
__global__ void ln_kernel(const float* __restrict__ x,
                          const float* __restrict__ gamma,
                          const float* __restrict__ beta) {
    int t = blockIdx.x;
    int wid = threadIdx.x >> 5, lane = threadIdx.x & 31;
    for (int bb = 0; bb < 4; bb++) {
        int b = wid * 4 + bb;
        float2 v = reinterpret_cast<const float2*>(x + ((size_t)b * Tm + t) * Fm)[lane];
        float s = v.x + v.y;
        float q = v.x * v.x + v.y * v.y;
        #pragma unroll
        for (int o = 16; o; o >>= 1) {
            s += __shfl_down_sync(0xffffffffu, s, o);
            q += __shfl_down_sync(0xffffffffu, q, o);
        }
        s = __shfl_sync(0xffffffffu, s, 0);
        q = __shfl_sync(0xffffffffu, q, 0);
        float mean = s * (1.f / 64.f);
        float var  = q * (1.f / 64.f) - mean * mean;
        float rstd = rsqrtf(var + 1e-3f);
        int f0 = 2 * lane;
        d_xnT[t * (Fm * Bm) + (f0    ) * Bm + b] = (v.x - mean) * rstd * gamma[f0]     + beta[f0];
        d_xnT[t * (Fm * Bm) + (f0 + 1) * Bm + b] = (v.y - mean) * rstd * gamma[f0 + 1] + beta[f0 + 1];
    }
}

// ---------------- GEMM1: xb1[t][c][b] = xnT[t] @ k1 + b1[0] ----------------
// one CTA per t; k1 (64x768, 192KB) staged fully in smem
#define SM1_FLOATS (Fm * G3 + Fm * Bm)
__global__ void gemm1_kernel(const float* __restrict__ k1,
                             const float* __restrict__ b1) {
    extern __shared__ float sm1[];
    float* ks = sm1;               // [f][c] 64*768
    float* As = sm1 + Fm * G3;     // [f][b] 64*32
    int t = blockIdx.x, tid = threadIdx.x;
    {
        const float4* src = reinterpret_cast<const float4*>(k1);
        float4* dst = reinterpret_cast<float4*>(ks);
        for (int i = tid; i < (Fm * G3) / 4; i += 256) dst[i] = src[i];
        const float4* a = reinterpret_cast<const float4*>(d_xnT + (size_t)t * Fm * Bm);
        float4* ad = reinterpret_cast<float4*>(As);
        for (int i = tid; i < (Fm * Bm) / 4; i += 256) ad[i] = a[i];
    }
    __syncthreads();
    int wid = tid >> 5, lane = tid & 31;
    for (int ch = 0; ch < 12; ch++) {
        int c0 = wid * 96 + ch * 8;
        float acc[8] = {0, 0, 0, 0, 0, 0, 0, 0};
        #pragma unroll 4
        for (int f = 0; f < Fm; f++) {
            float a = As[f * Bm + lane];
            float4 w0 = *reinterpret_cast<const float4*>(&ks[f * G3 + c0]);
            float4 w1 = *reinterpret_cast<const float4*>(&ks[f * G3 + c0 + 4]);
            acc[0] = fmaf(a, w0.x, acc[0]); acc[1] = fmaf(a, w0.y, acc[1]);
            acc[2] = fmaf(a, w0.z, acc[2]); acc[3] = fmaf(a, w0.w, acc[3]);
            acc[4] = fmaf(a, w1.x, acc[4]); acc[5] = fmaf(a, w1.y, acc[5]);
            acc[6] = fmaf(a, w1.z, acc[6]); acc[7] = fmaf(a, w1.w, acc[7]);
        }
        float* outp = d_xb1 + (size_t)t * G3 * Bm + (size_t)c0 * Bm + lane;
        #pragma unroll
        for (int i = 0; i < 8; i++) outp[i * Bm] = acc[i] + __ldg(&b1[c0 + i]);
    }
}

// ---------------- GEMM2: xb2[t][c][b] = h1[t] @ k2 + b2[0] -----------------
// 2 timesteps per CTA; weight c-tiles of 128 staged in smem
#define SM2_FLOATS (2 * Hm * Bm + Hm * 128)
__global__ void gemm2_kernel(const float* __restrict__ k2,
                             const float* __restrict__ b2) {
    extern __shared__ float sm2[];
    float* As = sm2;                 // 2 * [k][b]
    float* ws = sm2 + 2 * Hm * Bm;   // [k][128]
    int tid = threadIdx.x, wid = tid >> 5, lane = tid & 31;
    int t0 = blockIdx.x * 2;
    {
        const float4* a = reinterpret_cast<const float4*>(d_h1 + (size_t)t0 * Hm * Bm);
        float4* ad = reinterpret_cast<float4*>(As);
        for (int i = tid; i < (2 * Hm * Bm) / 4; i += 256) ad[i] = a[i];
    }
    for (int ct = 0; ct < 6; ct++) {
        __syncthreads();
        for (int i = tid; i < Hm * 32; i += 256) {  // 8192 float4s
            int k = i >> 5, c4 = i & 31;
            *reinterpret_cast<float4*>(&ws[k * 128 + c4 * 4]) =
                *reinterpret_cast<const float4*>(&k2[k * G3 + ct * 128 + c4 * 4]);
        }
        __syncthreads();
        int cw = wid * 16;
        float acc0[16], acc1[16];
        #pragma unroll
        for (int i = 0; i < 16; i++) { acc0[i] = 0.f; acc1[i] = 0.f; }
        #pragma unroll 2
        for (int k = 0; k < Hm; k++) {
            float a0 = As[k * Bm + lane];
            float a1 = As[Hm * Bm + k * Bm + lane];
            float w[16];
            const float* wrow = &ws[k * 128 + cw];
            *reinterpret_cast<float4*>(&w[0])  = *reinterpret_cast<const float4*>(wrow);
            *reinterpret_cast<float4*>(&w[4])  = *reinterpret_cast<const float4*>(wrow + 4);
            *reinterpret_cast<float4*>(&w[8])  = *reinterpret_cast<const float4*>(wrow + 8);
            *reinterpret_cast<float4*>(&w[12]) = *reinterpret_cast<const float4*>(wrow + 12);
            #pragma unroll
            for (int i = 0; i < 16; i++) {
                acc0[i] = fmaf(a0, w[i], acc0[i]);
                acc1[i] = fmaf(a1, w[i], acc1[i]);
            }
        }
        #pragma unroll
        for (int i = 0; i < 16; i++) {
            int c = ct * 128 + cw + i;
            float bias = __ldg(&b2[c]);
            d_xb2[(size_t)(t0    ) * G3 * Bm + (size_t)c * Bm + lane] = acc0[i] + bias;
            d_xb2[(size_t)(t0 + 1) * G3 * Bm + (size_t)c * Bm + lane] = acc1[i] + bias;
        }
    }
}

// ---------------- persistent GRU (grid-synced over T steps) ----------------
__global__ void __launch_bounds__(256, 1) gru_kernel(int which,
                          const float* __restrict__ rk,     // [256][768]
                          const float* __restrict__ bias2)  // inner bias row [768]
{
    const float* xb = which ? d_xb2 : d_xb1;
    float* hseq = which ? (float*)nullptr : d_h1;

    __shared__ __align__(16) float wsm[3 * JPC * Hm];  // [g][jl][k]
    __shared__ __align__(16) float hs[Hm * Bm];        // [k][b]
    __shared__ float ps[JPC * 3 * Bm];                 // k-split partials

    int tid = threadIdx.x, wid = tid >> 5, lane = tid & 31;
    int j0 = blockIdx.x * JPC;
    int jl = wid >> 1;          // local hidden unit
    int kh = wid & 1;           // k half
    int kbase = kh * 128;
    int j = j0 + jl;

    for (int idx = tid; idx < 3 * JPC * Hm; idx += 256) {
        int g = idx >> 10, jj = (idx >> 8) & 3, k = idx & 255;
        wsm[idx] = rk[k * G3 + g * Hm + j0 + jj];
    }
    float bz = bias2[j], br = bias2[Hm + j], bh = bias2[2 * Hm + j];

    // zero this CTA's slice of the read buffer for t=0
    for (int idx = tid; idx < JPC * Bm; idx += 256) d_hA[j0 * Bm + idx] = 0.f;

    __threadfence();
    __syncthreads();
    unsigned tgt = NCTA;
    if (tid == 0) {
        atomicAdd(&d_bar, 1u);
        while (*((volatile unsigned*)&d_bar) < tgt) {}
    }
    __syncthreads();

    const float* wz = wsm + jl * Hm;
    const float* wr = wsm + 1024 + jl * Hm;
    const float* wh = wsm + 2048 + jl * Hm;

    for (int t = 0; t < Tm; t++) {
        const float* hr = (t & 1) ? d_hB : d_hA;
        float*       hw = (t & 1) ? d_hA : d_hB;

        // stage h (bypass L1: buffer alternates between launches of same step parity)
        {
            const float4* src = reinterpret_cast<const float4*>(hr);
            float4* dst = reinterpret_cast<float4*>(hs);
            for (int i = tid; i < (Hm * Bm) / 4; i += 256) dst[i] = __ldcg(&src[i]);
        }
        // prefetch x-projection (gate warps only)
        float xz = 0.f, xr = 0.f, xh = 0.f;
        if (kh == 0) {
            const float* xp = xb + (size_t)t * G3 * Bm;
            xz = xp[(j         ) * Bm + lane];
            xr = xp[(Hm + j    ) * Bm + lane];
            xh = xp[(2 * Hm + j) * Bm + lane];
        }
        __syncthreads();
        float hold = (kh == 0) ? hs[j * Bm + lane] : 0.f;

        float az0 = 0.f, az1 = 0.f, ar0 = 0.f, ar1 = 0.f, ah0 = 0.f, ah1 = 0.f;
        #pragma unroll 8
        for (int k = kbase; k < kbase + 128; k += 4) {
            float4 z4 = *reinterpret_cast<const float4*>(wz + k);
            float4 r4 = *reinterpret_cast<const float4*>(wr + k);
            float4 h4 = *reinterpret_cast<const float4*>(wh + k);
            float v0 = hs[(k + 0) * Bm + lane];
            float v1 = hs[(k + 1) * Bm + lane];
            float v2 = hs[(k + 2) * Bm + lane];
            float v3 = hs[(k + 3) * Bm + lane];
            az0 = fmaf(v0, z4.x, az0); az1 = fmaf(v1, z4.y, az1);
            az0 = fmaf(v2, z4.z, az0); az1 = fmaf(v3, z4.w, az1);
            ar0 = fmaf(v0, r4.x, ar0); ar1 = fmaf(v1, r4.y, ar1);
            ar0 = fmaf(v2, r4.z, ar0); ar1 = fmaf(v3, r4.w, ar1);
            ah0 = fmaf(v0, h4.x, ah0); ah1 = fmaf(v1, h4.y, ah1);
            ah0 = fmaf(v2, h4.z, ah0); ah1 = fmaf(v3, h4.w, ah1);
        }
        float az = az0 + az1, ar = ar0 + ar1, ah = ah0 + ah1;
        if (kh == 1) {
            ps[(jl * 3 + 0) * Bm + lane] = az;
            ps[(jl * 3 + 1) * Bm + lane] = ar;
            ps[(jl * 3 + 2) * Bm + lane] = ah;
        }
        __syncthreads();
        if (kh == 0) {
            az += ps[(jl * 3 + 0) * Bm + lane] + bz;
            ar += ps[(jl * 3 + 1) * Bm + lane] + br;
            ah += ps[(jl * 3 + 2) * Bm + lane] + bh;
            float z  = 1.f / (1.f + __expf(-(xz + az)));
            float r  = 1.f / (1.f + __expf(-(xr + ar)));
            float hh = tanhf(xh + r * ah);
            float hn = z * hold + (1.f - z) * hh;
            hw[j * Bm + lane] = hn;
            if (hseq) hseq[(size_t)t * Hm * Bm + j * Bm + lane] = hn;
        }
        // grid barrier
        __threadfence();
        __syncthreads();
        tgt += NCTA;
        if (tid == 0) {
            atomicAdd(&d_bar, 1u);
            while (*((volatile unsigned*)&d_bar) < tgt) {}
        }
        __syncthreads();
    }
}

// ---------------- Dense: out[b][o] = h2 @ wd + bd --------------------------
__global__ void dense_kernel(const float* __restrict__ wd,
                             const float* __restrict__ bd,
                             float* __restrict__ out) {
    int gid = blockIdx.x * blockDim.x + threadIdx.x;   // 0..2047
    int b = gid >> 6, o = gid & 63;
    float acc = bd[o];
    #pragma unroll 8
    for (int k = 0; k < Hm; k++)
        acc = fmaf(d_hA[k * Bm + b], __ldg(&wd[k * OUTm + o]), acc);
    out[b * OUTm + o] = acc;
}

// ---------------- launch ----------------------------------------------------
extern "C" void kernel_launch(void* const* d_in, const int* in_sizes, int n_in,
                              void* d_out, int out_size) {
    const float* x     = (const float*)d_in[0];
    const float* gamma = (const float*)d_in[1];
    const float* beta  = (const float*)d_in[2];
    const float* k1    = (const float*)d_in[3];
    const float* rk1   = (const float*)d_in[4];
    const float* b1    = (const float*)d_in[5];
    const float* k2    = (const float*)d_in[6];
    const float* rk2   = (const float*)d_in[7];
    const float* b2    = (const float*)d_in[8];
    const float* wd    = (const float*)d_in[9];
    const float* bd    = (const float*)d_in[10];
    float* out = (float*)d_out;

    cudaFuncSetAttribute(gemm1_kernel, cudaFuncAttributeMaxDynamicSharedMemorySize,
                         SM1_FLOATS * sizeof(float));
    cudaFuncSetAttribute(gemm2_kernel, cudaFuncAttributeMaxDynamicSharedMemorySize,
                         SM2_FLOATS * sizeof(float));
    void* barp = nullptr;
    cudaGetSymbolAddress(&barp, d_bar);

    ln_kernel<<<Tm, 256>>>(x, gamma, beta);
    gemm1_kernel<<<Tm, 256, SM1_FLOATS * sizeof(float)>>>(k1, b1);
    cudaMemsetAsync(barp, 0, sizeof(unsigned));
    gru_kernel<<<NCTA, 256>>>(0, rk1, b1 + G3);       // writes d_h1, ends in d_hA
    gemm2_kernel<<<Tm / 2, 256, SM2_FLOATS * sizeof(float)>>>(k2, b2);
    cudaMemsetAsync(barp, 0, sizeof(unsigned));
    gru_kernel<<<NCTA, 256>>>(1, rk2, b2 + G3);       // final state in d_hA
    dense_kernel<<<(Bm * OUTm) / 256, 256>>>(wd, bd, out);
}